// round 2
// baseline (speedup 1.0000x reference)
#include <cuda_runtime.h>
#include <math.h>

#define BB      32768
#define IN_DIM  784
#define H0      512
#define H1      1024
#define KCODES  128
#define DDIM    128
#define NSLOT   8

// Scratch (no cudaMalloc allowed): h1 and h3 activations [B, 512] each.
__device__ float g_h1[(size_t)BB * H0];
__device__ float g_h3[(size_t)BB * H0];

// ---------------------------------------------------------------------------
// Generic tiled SGEMM with fused bias + activation.
// C[M,N] = act(A[M,K] @ B[K,N] + bias[N])
// BM=BN=128, BK=16, 256 threads, 8x8 register tile per thread.
// Requirements: M % 128 == 0, K % 16 == 0, N % 4 == 0 (true for all 4 GEMMs).
// ACT: 0 = none, 1 = relu, 2 = tanh
// ---------------------------------------------------------------------------
template<int ACT>
__global__ __launch_bounds__(256, 2)
void sgemm_bias_act(const float* __restrict__ A, const float* __restrict__ B,
                    const float* __restrict__ bias, float* __restrict__ C,
                    int M, int N, int K)
{
    __shared__ float As[16 * 132];   // transposed A tile, padded stride 132
    __shared__ float Bs[16 * 128];

    const int tid  = threadIdx.x;
    const int tx   = tid & 15;       // N direction
    const int ty   = tid >> 4;       // M direction
    const int row0 = blockIdx.y * 128;
    const int col0 = blockIdx.x * 128;

    float acc[8][8];
    #pragma unroll
    for (int i = 0; i < 8; i++)
        #pragma unroll
        for (int j = 0; j < 8; j++) acc[i][j] = 0.0f;

    for (int k0 = 0; k0 < K; k0 += 16) {
        // Load A tile (128x16) and B tile (16x128), 2 float4 each per thread.
        #pragma unroll
        for (int i = 0; i < 2; i++) {
            int idx = tid + i * 256;
            // A: row = idx/4, float4-col = idx%4
            int ar = idx >> 2;
            int ac = (idx & 3) * 4;
            float4 va = *(const float4*)(A + (size_t)(row0 + ar) * K + k0 + ac);
            As[(ac + 0) * 132 + ar] = va.x;
            As[(ac + 1) * 132 + ar] = va.y;
            As[(ac + 2) * 132 + ar] = va.z;
            As[(ac + 3) * 132 + ar] = va.w;
            // B: row = idx/32, float4-col = idx%32
            int br  = idx >> 5;
            int bc  = (idx & 31) * 4;
            int col = col0 + bc;
            float4 vb = make_float4(0.f, 0.f, 0.f, 0.f);
            if (col < N)
                vb = *(const float4*)(B + (size_t)(k0 + br) * N + col);
            *(float4*)(Bs + br * 128 + bc) = vb;
        }
        __syncthreads();

        #pragma unroll
        for (int kk = 0; kk < 16; kk++) {
            float a[8], b[8];
            *(float4*)(a)     = *(const float4*)(As + kk * 132 + ty * 8);
            *(float4*)(a + 4) = *(const float4*)(As + kk * 132 + ty * 8 + 4);
            *(float4*)(b)     = *(const float4*)(Bs + kk * 128 + tx * 8);
            *(float4*)(b + 4) = *(const float4*)(Bs + kk * 128 + tx * 8 + 4);
            #pragma unroll
            for (int i = 0; i < 8; i++)
                #pragma unroll
                for (int j = 0; j < 8; j++)
                    acc[i][j] = fmaf(a[i], b[j], acc[i][j]);
        }
        __syncthreads();
    }

    // Epilogue: bias + activation, guarded float4 stores (N % 4 == 0).
    #pragma unroll
    for (int i = 0; i < 8; i++) {
        int row = row0 + ty * 8 + i;
        #pragma unroll
        for (int j4 = 0; j4 < 2; j4++) {
            int col = col0 + tx * 8 + j4 * 4;
            if (col < N) {
                float4 bv = *(const float4*)(bias + col);
                float4 r;
                r.x = acc[i][j4 * 4 + 0] + bv.x;
                r.y = acc[i][j4 * 4 + 1] + bv.y;
                r.z = acc[i][j4 * 4 + 2] + bv.z;
                r.w = acc[i][j4 * 4 + 3] + bv.w;
                if (ACT == 1) {
                    r.x = fmaxf(r.x, 0.f); r.y = fmaxf(r.y, 0.f);
                    r.z = fmaxf(r.z, 0.f); r.w = fmaxf(r.w, 0.f);
                } else if (ACT == 2) {
                    r.x = tanhf(r.x); r.y = tanhf(r.y);
                    r.z = tanhf(r.z); r.w = tanhf(r.w);
                }
                *(float4*)(C + (size_t)row * N + col) = r;
            }
        }
    }
}

// ---------------------------------------------------------------------------
// VQ: for each sample b and slot n (z[d] = z_e[b, d*8+n]), find the codebook
// column k minimizing ||z - E[:,k]||^2, tie -> lowest k (matches jnp.argmin),
// then scatter E[:,kmin] into zq[b, d*8+n].
//
// Numerically robust argmin: fast fp32 pass (4 partial accumulators) finds
// top-2 candidates; if their gap < TAU (far above fp32 accumulation error,
// so the true best is guaranteed among the fp32 top-2), recompute both exact
// squared distances in double and pick the true argmin.
//
// E cached in smem with stride 129 (conflict-free rows AND columns).
// 256 threads: group g = tid/128 handles slot n = it*2+g, one code per thread.
// ---------------------------------------------------------------------------
__global__ __launch_bounds__(256)
void vq_kernel(const float* __restrict__ z_e, const float* __restrict__ E,
               float* __restrict__ zq, int rows_per_block)
{
    extern __shared__ float sm[];
    float* Es   = sm;                 // 128*129 floats
    float* zrow = Es + 128 * 129;     // 1024 floats

    __shared__ float s_e2[128];
    __shared__ float s_rv[8];
    __shared__ int   s_ri[8];
    __shared__ float s_m1v[2];
    __shared__ int   s_m1i[2];
    __shared__ int   s_kmin[8];

    const int tid  = threadIdx.x;
    const int lane = tid & 31;
    const int warp = tid >> 5;
    const int k    = tid & 127;
    const int g    = tid >> 7;        // 0 or 1
    const float INF = __int_as_float(0x7f800000);
    const float TAU = 0.05f;

    // Stage codebook into smem.
    for (int i = tid; i < 128 * 128; i += 256) {
        int d  = i >> 7;
        int kk = i & 127;
        Es[d * 129 + kk] = E[i];
    }
    __syncthreads();

    // ||E_k||^2 per code.
    if (tid < 128) {
        float s = 0.f;
        #pragma unroll 8
        for (int d = 0; d < 128; d++) {
            float e = Es[d * 129 + tid];
            s = fmaf(e, e, s);
        }
        s_e2[tid] = s;
    }
    __syncthreads();

    const int b0 = blockIdx.x * rows_per_block;
    for (int r = 0; r < rows_per_block; r++) {
        const int b = b0 + r;
        for (int i = tid; i < 1024; i += 256)
            zrow[i] = z_e[(size_t)b * 1024 + i];
        __syncthreads();

        for (int it = 0; it < 4; it++) {
            const int n = it * 2 + g;
            // fp32 distance, 4 partial accumulators (lower rounding error).
            float a0 = 0.f, a1 = 0.f, a2 = 0.f, a3 = 0.f;
            #pragma unroll 8
            for (int d = 0; d < 128; d += 4) {
                a0 = fmaf(Es[(d + 0) * 129 + k], zrow[(d + 0) * 8 + n], a0);
                a1 = fmaf(Es[(d + 1) * 129 + k], zrow[(d + 1) * 8 + n], a1);
                a2 = fmaf(Es[(d + 2) * 129 + k], zrow[(d + 2) * 8 + n], a2);
                a3 = fmaf(Es[(d + 3) * 129 + k], zrow[(d + 3) * 8 + n], a3);
            }
            const float dist = s_e2[k] - 2.0f * ((a0 + a1) + (a2 + a3));

            // ---- Pass A: argmin (tie -> lowest index) ----
            float v = dist; int bi = k;
            #pragma unroll
            for (int off = 16; off > 0; off >>= 1) {
                float ov = __shfl_down_sync(0xffffffffu, v,  off);
                int   oi = __shfl_down_sync(0xffffffffu, bi, off);
                if (ov < v || (ov == v && oi < bi)) { v = ov; bi = oi; }
            }
            if (lane == 0) { s_rv[warp] = v; s_ri[warp] = bi; }
            __syncthreads();
            if (tid < 2) {
                int base = tid * 4;
                float bv = s_rv[base]; int bk = s_ri[base];
                #pragma unroll
                for (int w2 = 1; w2 < 4; w2++) {
                    float vv = s_rv[base + w2]; int kk2 = s_ri[base + w2];
                    if (vv < bv || (vv == bv && kk2 < bk)) { bv = vv; bk = kk2; }
                }
                s_m1v[tid] = bv; s_m1i[tid] = bk;
            }
            __syncthreads();

            // ---- Pass B: runner-up (exclude idx1) ----
            const int idx1 = s_m1i[g];
            float v2 = (k == idx1) ? INF : dist; int bi2 = k;
            #pragma unroll
            for (int off = 16; off > 0; off >>= 1) {
                float ov = __shfl_down_sync(0xffffffffu, v2,  off);
                int   oi = __shfl_down_sync(0xffffffffu, bi2, off);
                if (ov < v2 || (ov == v2 && oi < bi2)) { v2 = ov; bi2 = oi; }
            }
            if (lane == 0) { s_rv[warp] = v2; s_ri[warp] = bi2; }
            __syncthreads();
            if (tid < 2) {
                int base = tid * 4;
                float bv2 = s_rv[base]; int bk2 = s_ri[base];
                #pragma unroll
                for (int w2 = 1; w2 < 4; w2++) {
                    float vv = s_rv[base + w2]; int kk2 = s_ri[base + w2];
                    if (vv < bv2 || (vv == bv2 && kk2 < bk2)) { bv2 = vv; bk2 = kk2; }
                }
                const int slot = it * 2 + tid;
                int i1 = s_m1i[tid], i2 = bk2;
                int kmin = i1;
                if (bv2 - s_m1v[tid] < TAU) {
                    // Near-tie: exact squared distances in double.
                    double d1 = 0.0, d2 = 0.0;
                    for (int d = 0; d < 128; d++) {
                        double zd = (double)zrow[d * 8 + slot];
                        double t1 = zd - (double)Es[d * 129 + i1];
                        double t2 = zd - (double)Es[d * 129 + i2];
                        d1 += t1 * t1;
                        d2 += t2 * t2;
                    }
                    if (d2 < d1 || (d2 == d1 && i2 < i1)) kmin = i2;
                }
                s_kmin[slot] = kmin;
            }
            __syncthreads();
        }

        // Gather quantized row: zq[b, d*8+n] = E[d, kmin[n]]  (coalesced stores).
        for (int j = tid; j < 1024; j += 256) {
            int d = j >> 3;
            int n = j & 7;
            zq[(size_t)b * 1024 + j] = Es[d * 129 + s_kmin[n]];
        }
        __syncthreads();
    }
}

// ---------------------------------------------------------------------------
// Launch: out layout = [recon (B*784) | z_e (B*1024) | emb (B*1024)].
// emb region doubles as z_q (identical flat layout), feeding GEMM3 directly.
// ---------------------------------------------------------------------------
extern "C" void kernel_launch(void* const* d_in, const int* in_sizes, int n_in,
                              void* d_out, int out_size)
{
    const float* x  = (const float*)d_in[0];
    const float* W1 = (const float*)d_in[1];
    const float* b1 = (const float*)d_in[2];
    const float* W2 = (const float*)d_in[3];
    const float* b2 = (const float*)d_in[4];
    const float* W3 = (const float*)d_in[5];
    const float* b3 = (const float*)d_in[6];
    const float* W4 = (const float*)d_in[7];
    const float* b4 = (const float*)d_in[8];
    const float* E  = (const float*)d_in[9];

    float* out   = (float*)d_out;
    float* recon = out;
    float* z_e   = out + (size_t)BB * IN_DIM;
    float* emb   = z_e + (size_t)BB * H1;     // == z_q flat

    float *h1p, *h3p;
    cudaGetSymbolAddress((void**)&h1p, g_h1);
    cudaGetSymbolAddress((void**)&h3p, g_h3);

    const dim3 blk(256);

    // G1: h1 = relu(x @ W1 + b1)
    sgemm_bias_act<1><<<dim3(H0 / 128, BB / 128), blk>>>(x, W1, b1, h1p, BB, H0, IN_DIM);
    // G2: z_e = h1 @ W2 + b2  (straight into d_out)
    sgemm_bias_act<0><<<dim3(H1 / 128, BB / 128), blk>>>(h1p, W2, b2, z_e, BB, H1, H0);

    // VQ: idx = argmin_k ||z - E_k||^2, emb/z_q = E[:, idx]
    const int smem = (128 * 129 + 1024) * (int)sizeof(float);
    cudaFuncSetAttribute(vq_kernel, cudaFuncAttributeMaxDynamicSharedMemorySize, smem);
    vq_kernel<<<2048, 256, smem>>>(z_e, E, emb, BB / 2048);

    // G3: h3 = relu(z_q @ W3 + b3)
    sgemm_bias_act<1><<<dim3(H0 / 128, BB / 128), blk>>>(emb, W3, b3, h3p, BB, H0, H1);
    // G4: recon = tanh(h3 @ W4 + b4)
    sgemm_bias_act<2><<<dim3((IN_DIM + 127) / 128, BB / 128), blk>>>(h3p, W4, b4, recon, BB, IN_DIM, H0);
}

// round 3
// speedup vs baseline: 1.0023x; 1.0023x over previous
#include <cuda_runtime.h>
#include <math.h>

#define BB      32768
#define IN_DIM  784
#define H0      512
#define H1      1024
#define KCODES  128
#define DDIM    128
#define NSLOT   8

// Scratch (no cudaMalloc allowed): h1 and h3 activations [B, 512] each.
__device__ float g_h1[(size_t)BB * H0];
__device__ float g_h3[(size_t)BB * H0];

// ---------------------------------------------------------------------------
// Generic tiled SGEMM with fused bias + activation.
// C[M,N] = act(A[M,K] @ B[K,N] + bias[N])
// BM=BN=128, BK=16, 256 threads, 8x8 register tile per thread.
// Requirements: M % 128 == 0, K % 16 == 0, N % 4 == 0 (true for all 4 GEMMs).
// ACT: 0 = none, 1 = relu, 2 = tanh
// ---------------------------------------------------------------------------
template<int ACT>
__global__ __launch_bounds__(256, 2)
void sgemm_bias_act(const float* __restrict__ A, const float* __restrict__ B,
                    const float* __restrict__ bias, float* __restrict__ C,
                    int M, int N, int K)
{
    __shared__ float As[16 * 132];   // transposed A tile, padded stride 132
    __shared__ float Bs[16 * 128];

    const int tid  = threadIdx.x;
    const int tx   = tid & 15;       // N direction
    const int ty   = tid >> 4;       // M direction
    const int row0 = blockIdx.y * 128;
    const int col0 = blockIdx.x * 128;

    float acc[8][8];
    #pragma unroll
    for (int i = 0; i < 8; i++)
        #pragma unroll
        for (int j = 0; j < 8; j++) acc[i][j] = 0.0f;

    for (int k0 = 0; k0 < K; k0 += 16) {
        // Load A tile (128x16) and B tile (16x128), 2 float4 each per thread.
        #pragma unroll
        for (int i = 0; i < 2; i++) {
            int idx = tid + i * 256;
            // A: row = idx/4, float4-col = idx%4
            int ar = idx >> 2;
            int ac = (idx & 3) * 4;
            float4 va = *(const float4*)(A + (size_t)(row0 + ar) * K + k0 + ac);
            As[(ac + 0) * 132 + ar] = va.x;
            As[(ac + 1) * 132 + ar] = va.y;
            As[(ac + 2) * 132 + ar] = va.z;
            As[(ac + 3) * 132 + ar] = va.w;
            // B: row = idx/32, float4-col = idx%32
            int br  = idx >> 5;
            int bc  = (idx & 31) * 4;
            int col = col0 + bc;
            float4 vb = make_float4(0.f, 0.f, 0.f, 0.f);
            if (col < N)
                vb = *(const float4*)(B + (size_t)(k0 + br) * N + col);
            *(float4*)(Bs + br * 128 + bc) = vb;
        }
        __syncthreads();

        #pragma unroll
        for (int kk = 0; kk < 16; kk++) {
            float a[8], b[8];
            *(float4*)(a)     = *(const float4*)(As + kk * 132 + ty * 8);
            *(float4*)(a + 4) = *(const float4*)(As + kk * 132 + ty * 8 + 4);
            *(float4*)(b)     = *(const float4*)(Bs + kk * 128 + tx * 8);
            *(float4*)(b + 4) = *(const float4*)(Bs + kk * 128 + tx * 8 + 4);
            #pragma unroll
            for (int i = 0; i < 8; i++)
                #pragma unroll
                for (int j = 0; j < 8; j++)
                    acc[i][j] = fmaf(a[i], b[j], acc[i][j]);
        }
        __syncthreads();
    }

    // Epilogue: bias + activation, guarded float4 stores (N % 4 == 0).
    #pragma unroll
    for (int i = 0; i < 8; i++) {
        int row = row0 + ty * 8 + i;
        #pragma unroll
        for (int j4 = 0; j4 < 2; j4++) {
            int col = col0 + tx * 8 + j4 * 4;
            if (col < N) {
                float4 bv = *(const float4*)(bias + col);
                float4 r;
                r.x = acc[i][j4 * 4 + 0] + bv.x;
                r.y = acc[i][j4 * 4 + 1] + bv.y;
                r.z = acc[i][j4 * 4 + 2] + bv.z;
                r.w = acc[i][j4 * 4 + 3] + bv.w;
                if (ACT == 1) {
                    r.x = fmaxf(r.x, 0.f); r.y = fmaxf(r.y, 0.f);
                    r.z = fmaxf(r.z, 0.f); r.w = fmaxf(r.w, 0.f);
                } else if (ACT == 2) {
                    r.x = tanhf(r.x); r.y = tanhf(r.y);
                    r.z = tanhf(r.z); r.w = tanhf(r.w);
                }
                *(float4*)(C + (size_t)row * N + col) = r;
            }
        }
    }
}

// ---------------------------------------------------------------------------
// VQ: for each sample b and slot n (z[d] = z_e[b, d*8+n]), find the codebook
// column k minimizing ||z - E[:,k]||^2, tie -> lowest k (matches jnp.argmin),
// then scatter E[:,kmin] into zq[b, d*8+n].
//
// Numerically robust argmin: fast fp32 pass (4 partial accumulators) finds
// top-2 candidates; if their gap < TAU (far above fp32 accumulation error,
// so the true best is guaranteed among the fp32 top-2), recompute both exact
// squared distances in double and pick the true argmin.
//
// E cached in smem with stride 129 (conflict-free rows AND columns).
// 256 threads: group g = tid/128 handles slot n = it*2+g, one code per thread.
// ---------------------------------------------------------------------------
__global__ __launch_bounds__(256)
void vq_kernel(const float* __restrict__ z_e, const float* __restrict__ E,
               float* __restrict__ zq, int rows_per_block)
{
    extern __shared__ float sm[];
    float* Es   = sm;                 // 128*129 floats
    float* zrow = Es + 128 * 129;     // 1024 floats

    __shared__ float s_e2[128];
    __shared__ float s_rv[8];
    __shared__ int   s_ri[8];
    __shared__ float s_m1v[2];
    __shared__ int   s_m1i[2];
    __shared__ int   s_kmin[8];

    const int tid  = threadIdx.x;
    const int lane = tid & 31;
    const int warp = tid >> 5;
    const int k    = tid & 127;
    const int g    = tid >> 7;        // 0 or 1
    const float INF = __int_as_float(0x7f800000);
    const float TAU = 0.05f;

    // Stage codebook into smem.
    for (int i = tid; i < 128 * 128; i += 256) {
        int d  = i >> 7;
        int kk = i & 127;
        Es[d * 129 + kk] = E[i];
    }
    __syncthreads();

    // ||E_k||^2 per code.
    if (tid < 128) {
        float s = 0.f;
        #pragma unroll 8
        for (int d = 0; d < 128; d++) {
            float e = Es[d * 129 + tid];
            s = fmaf(e, e, s);
        }
        s_e2[tid] = s;
    }
    __syncthreads();

    const int b0 = blockIdx.x * rows_per_block;
    for (int r = 0; r < rows_per_block; r++) {
        const int b = b0 + r;
        for (int i = tid; i < 1024; i += 256)
            zrow[i] = z_e[(size_t)b * 1024 + i];
        __syncthreads();

        for (int it = 0; it < 4; it++) {
            const int n = it * 2 + g;
            // fp32 distance, 4 partial accumulators (lower rounding error).
            float a0 = 0.f, a1 = 0.f, a2 = 0.f, a3 = 0.f;
            #pragma unroll 8
            for (int d = 0; d < 128; d += 4) {
                a0 = fmaf(Es[(d + 0) * 129 + k], zrow[(d + 0) * 8 + n], a0);
                a1 = fmaf(Es[(d + 1) * 129 + k], zrow[(d + 1) * 8 + n], a1);
                a2 = fmaf(Es[(d + 2) * 129 + k], zrow[(d + 2) * 8 + n], a2);
                a3 = fmaf(Es[(d + 3) * 129 + k], zrow[(d + 3) * 8 + n], a3);
            }
            const float dist = s_e2[k] - 2.0f * ((a0 + a1) + (a2 + a3));

            // ---- Pass A: argmin (tie -> lowest index) ----
            float v = dist; int bi = k;
            #pragma unroll
            for (int off = 16; off > 0; off >>= 1) {
                float ov = __shfl_down_sync(0xffffffffu, v,  off);
                int   oi = __shfl_down_sync(0xffffffffu, bi, off);
                if (ov < v || (ov == v && oi < bi)) { v = ov; bi = oi; }
            }
            if (lane == 0) { s_rv[warp] = v; s_ri[warp] = bi; }
            __syncthreads();
            if (tid < 2) {
                int base = tid * 4;
                float bv = s_rv[base]; int bk = s_ri[base];
                #pragma unroll
                for (int w2 = 1; w2 < 4; w2++) {
                    float vv = s_rv[base + w2]; int kk2 = s_ri[base + w2];
                    if (vv < bv || (vv == bv && kk2 < bk)) { bv = vv; bk = kk2; }
                }
                s_m1v[tid] = bv; s_m1i[tid] = bk;
            }
            __syncthreads();

            // ---- Pass B: runner-up (exclude idx1) ----
            const int idx1 = s_m1i[g];
            float v2 = (k == idx1) ? INF : dist; int bi2 = k;
            #pragma unroll
            for (int off = 16; off > 0; off >>= 1) {
                float ov = __shfl_down_sync(0xffffffffu, v2,  off);
                int   oi = __shfl_down_sync(0xffffffffu, bi2, off);
                if (ov < v2 || (ov == v2 && oi < bi2)) { v2 = ov; bi2 = oi; }
            }
            if (lane == 0) { s_rv[warp] = v2; s_ri[warp] = bi2; }
            __syncthreads();
            if (tid < 2) {
                int base = tid * 4;
                float bv2 = s_rv[base]; int bk2 = s_ri[base];
                #pragma unroll
                for (int w2 = 1; w2 < 4; w2++) {
                    float vv = s_rv[base + w2]; int kk2 = s_ri[base + w2];
                    if (vv < bv2 || (vv == bv2 && kk2 < bk2)) { bv2 = vv; bk2 = kk2; }
                }
                const int slot = it * 2 + tid;
                int i1 = s_m1i[tid], i2 = bk2;
                int kmin = i1;
                if (bv2 - s_m1v[tid] < TAU) {
                    // Near-tie: exact squared distances in double.
                    double d1 = 0.0, d2 = 0.0;
                    for (int d = 0; d < 128; d++) {
                        double zd = (double)zrow[d * 8 + slot];
                        double t1 = zd - (double)Es[d * 129 + i1];
                        double t2 = zd - (double)Es[d * 129 + i2];
                        d1 += t1 * t1;
                        d2 += t2 * t2;
                    }
                    if (d2 < d1 || (d2 == d1 && i2 < i1)) kmin = i2;
                }
                s_kmin[slot] = kmin;
            }
            __syncthreads();
        }

        // Gather quantized row: zq[b, d*8+n] = E[d, kmin[n]]  (coalesced stores).
        for (int j = tid; j < 1024; j += 256) {
            int d = j >> 3;
            int n = j & 7;
            zq[(size_t)b * 1024 + j] = Es[d * 129 + s_kmin[n]];
        }
        __syncthreads();
    }
}

// ---------------------------------------------------------------------------
// Launch: out layout = [recon (B*784) | z_e (B*1024) | emb (B*1024)].
// emb region doubles as z_q (identical flat layout), feeding GEMM3 directly.
// ---------------------------------------------------------------------------
extern "C" void kernel_launch(void* const* d_in, const int* in_sizes, int n_in,
                              void* d_out, int out_size)
{
    const float* x  = (const float*)d_in[0];
    const float* W1 = (const float*)d_in[1];
    const float* b1 = (const float*)d_in[2];
    const float* W2 = (const float*)d_in[3];
    const float* b2 = (const float*)d_in[4];
    const float* W3 = (const float*)d_in[5];
    const float* b3 = (const float*)d_in[6];
    const float* W4 = (const float*)d_in[7];
    const float* b4 = (const float*)d_in[8];
    const float* E  = (const float*)d_in[9];

    float* out   = (float*)d_out;
    float* recon = out;
    float* z_e   = out + (size_t)BB * IN_DIM;
    float* emb   = z_e + (size_t)BB * H1;     // == z_q flat

    float *h1p, *h3p;
    cudaGetSymbolAddress((void**)&h1p, g_h1);
    cudaGetSymbolAddress((void**)&h3p, g_h3);

    const dim3 blk(256);

    // G1: h1 = relu(x @ W1 + b1)
    sgemm_bias_act<1><<<dim3(H0 / 128, BB / 128), blk>>>(x, W1, b1, h1p, BB, H0, IN_DIM);
    // G2: z_e = h1 @ W2 + b2  (straight into d_out)
    sgemm_bias_act<0><<<dim3(H1 / 128, BB / 128), blk>>>(h1p, W2, b2, z_e, BB, H1, H0);

    // VQ: idx = argmin_k ||z - E_k||^2, emb/z_q = E[:, idx]
    const int smem = (128 * 129 + 1024) * (int)sizeof(float);
    cudaFuncSetAttribute(vq_kernel, cudaFuncAttributeMaxDynamicSharedMemorySize, smem);
    vq_kernel<<<2048, 256, smem>>>(z_e, E, emb, BB / 2048);

    // G3: h3 = relu(z_q @ W3 + b3)
    sgemm_bias_act<1><<<dim3(H0 / 128, BB / 128), blk>>>(emb, W3, b3, h3p, BB, H0, H1);
    // G4: recon = tanh(h3 @ W4 + b4)
    sgemm_bias_act<2><<<dim3((IN_DIM + 127) / 128, BB / 128), blk>>>(h3p, W4, b4, recon, BB, IN_DIM, H0);
}

// round 6
// speedup vs baseline: 1.0478x; 1.0454x over previous
#include <cuda_runtime.h>
#include <cuda_bf16.h>
#include <math.h>
#include <stdint.h>

#define BB      32768
#define IN_DIM  784
#define H0      512
#define H1      1024

__device__ float g_h1[(size_t)BB * H0];
__device__ float g_h3[(size_t)BB * H0];

__device__ __forceinline__ uint32_t smem_u32(const void* p) {
    uint32_t a;
    asm("{ .reg .u64 t; cvta.to.shared.u64 t, %1; cvt.u32.u64 %0, t; }"
        : "=r"(a) : "l"(p));
    return a;
}
__device__ __forceinline__ void ldsm4(uint32_t* r, uint32_t a) {
    asm volatile("ldmatrix.sync.aligned.m8n8.x4.shared.b16 {%0,%1,%2,%3}, [%4];"
                 : "=r"(r[0]), "=r"(r[1]), "=r"(r[2]), "=r"(r[3]) : "r"(a));
}
__device__ __forceinline__ void mma16816(float* d, const uint32_t* a, const uint32_t* b) {
    asm volatile("mma.sync.aligned.m16n8k16.row.col.f32.bf16.bf16.f32 "
                 "{%0,%1,%2,%3}, {%4,%5,%6,%7}, {%8,%9}, {%0,%1,%2,%3};"
                 : "+f"(d[0]), "+f"(d[1]), "+f"(d[2]), "+f"(d[3])
                 : "r"(a[0]), "r"(a[1]), "r"(a[2]), "r"(a[3]), "r"(b[0]), "r"(b[1]));
}

// fp32 -> 3-way bf16 split (h+m+l ~ 24 mantissa bits)
__device__ __forceinline__ void split3(float a, uint32_t& h, uint32_t& m, uint32_t& l) {
    __nv_bfloat16 bh = __float2bfloat16(a);
    float r = a - __bfloat162float(bh);
    __nv_bfloat16 bm = __float2bfloat16(r);
    __nv_bfloat16 bl = __float2bfloat16(r - __bfloat162float(bm));
    h = (uint32_t)__bfloat16_as_ushort(bh);
    m = (uint32_t)__bfloat16_as_ushort(bm);
    l = (uint32_t)__bfloat16_as_ushort(bl);
}

// ===========================================================================
// HMMA GEMM: C[M,N] = act(A[M,K] @ B[K,N] + bias[N]), fp32 via bf16 splits.
// CTA 128x128, 256 thr (8 warps of 64x32), K-chunk 32, double-buffered smem,
// reg-prefetch pipeline.
// TWO accumulator banks: bank 0 gets only the h*h products (one rounding per
// term at full magnitude, fp32-FMA error class); bank 1 gets all cross terms
// (magnitude ~2^-8 of result -> its roundings are negligible). Summed once
// in the epilogue. NS=3 -> combos hh | hm,mh,mm,hl,lh; NS=2 -> hh | hm,mh.
// M%128==0, K%16==0. ACT: 0 none, 1 relu, 2 tanh.
// Smem per buffer: NS*2 planes of [128][40] bf16 (pad 40: ldmatrix
// conflict-free).
// ===========================================================================
template<int NS, int ACT>
__global__ __launch_bounds__(256)
void hmma_gemm(const float* __restrict__ A, const float* __restrict__ Bw,
               const float* __restrict__ bias, float* __restrict__ C,
               int M, int N, int K)
{
    constexpr int PL    = 128 * 40 * 2;      // 10240 B per plane
    constexpr int BUFSZ = NS * 2 * PL;
    extern __shared__ char dsm[];
    const uint32_t smemU = smem_u32(dsm);
    __shared__ float sbias[128];

    const int tid  = threadIdx.x;
    const int warp = tid >> 5;
    const int lane = tid & 31;
    const int row0 = blockIdx.y * 128;
    const int col0 = blockIdx.x * 128;
    const int m_base = (warp >> 2) * 64;     // 0 or 64
    const int n_base = (warp & 3) * 32;      // 0,32,64,96

    {
        int c = col0 + tid;
        if (tid < 128) sbias[tid] = (c < N) ? bias[c] : 0.0f;
    }

    // combos (sa, sb); combo 0 (hh) -> bank 0, rest -> bank 1.
    const int CA[6] = {0, 0, 1, 1, 0, 2};
    const int CB[6] = {0, 1, 0, 1, 2, 0};
    const int NCOMBO = (NS == 3) ? 6 : 3;

    float acc[2][4][4][4];
    #pragma unroll
    for (int bk = 0; bk < 2; bk++)
        #pragma unroll
        for (int i = 0; i < 4; i++)
            #pragma unroll
            for (int j = 0; j < 4; j++)
                #pragma unroll
                for (int q = 0; q < 4; q++) acc[bk][i][j][q] = 0.0f;

    const int NC = (K + 31) >> 5;

    const int arow  = tid >> 1;               // A/Bt smem row owned by thread
    const int ahalf = (tid & 1);              // which 16-col half
    float fa[16], fb[16];

    auto ldg_chunk = [&](int c) {
        const int k0 = c << 5;
        #pragma unroll
        for (int q = 0; q < 4; q++) {
            int kc = k0 + ahalf * 16 + q * 4;
            float4 v = make_float4(0.f, 0.f, 0.f, 0.f);
            if (kc < K)
                v = *(const float4*)(A + (size_t)(row0 + arow) * K + kc);
            fa[q * 4 + 0] = v.x; fa[q * 4 + 1] = v.y;
            fa[q * 4 + 2] = v.z; fa[q * 4 + 3] = v.w;
        }
        const int  n   = arow;
        const bool nok = (col0 + n) < N;
        #pragma unroll
        for (int j = 0; j < 16; j++) {
            int kk = k0 + ahalf * 16 + j;
            fb[j] = (nok && kk < K) ? Bw[(size_t)kk * N + col0 + n] : 0.0f;
        }
    };
    auto store_chunk = [&](int buf) {
        char* bp = dsm + buf * BUFSZ;
        const uint32_t ao = (uint32_t)arow * 80u + (uint32_t)ahalf * 32u;
        #pragma unroll
        for (int q = 0; q < 8; q++) {
            uint32_t h0, m0, l0, h1, m1, l1;
            split3(fa[q * 2 + 0], h0, m0, l0);
            split3(fa[q * 2 + 1], h1, m1, l1);
            *(uint32_t*)(bp + 0 * PL + ao + q * 4) = h0 | (h1 << 16);
            *(uint32_t*)(bp + 1 * PL + ao + q * 4) = m0 | (m1 << 16);
            if (NS == 3)
                *(uint32_t*)(bp + 2 * PL + ao + q * 4) = l0 | (l1 << 16);
        }
        char* bpB = bp + NS * PL;
        #pragma unroll
        for (int q = 0; q < 8; q++) {
            uint32_t h0, m0, l0, h1, m1, l1;
            split3(fb[q * 2 + 0], h0, m0, l0);
            split3(fb[q * 2 + 1], h1, m1, l1);
            *(uint32_t*)(bpB + 0 * PL + ao + q * 4) = h0 | (h1 << 16);
            *(uint32_t*)(bpB + 1 * PL + ao + q * 4) = m0 | (m1 << 16);
            if (NS == 3)
                *(uint32_t*)(bpB + 2 * PL + ao + q * 4) = l0 | (l1 << 16);
        }
    };

    const int lgrp = lane >> 3, lrow = lane & 7;
    const int d0 = (lgrp & 1) * 8;
    const int dk = (lgrp >> 1) * 8;

    ldg_chunk(0);
    store_chunk(0);
    __syncthreads();

    for (int c = 0; c < NC; c++) {
        if (c + 1 < NC) ldg_chunk(c + 1);

        const uint32_t bu = smemU + (c & 1) * BUFSZ;
        #pragma unroll
        for (int ks = 0; ks < 2; ks++) {
            const uint32_t kbyte = (uint32_t)(ks * 16 + dk) * 2u;
            uint32_t br[NS][2][4];
            #pragma unroll
            for (int s = 0; s < NS; s++)
                #pragma unroll
                for (int ni = 0; ni < 2; ni++) {
                    uint32_t ad = bu + (NS + s) * PL
                                + (uint32_t)(n_base + ni * 16 + d0 + lrow) * 80u + kbyte;
                    ldsm4(br[s][ni], ad);
                }
            #pragma unroll
            for (int mi = 0; mi < 4; mi++) {
                uint32_t ar[NS][4];
                #pragma unroll
                for (int s = 0; s < NS; s++) {
                    uint32_t ad = bu + s * PL
                                + (uint32_t)(m_base + mi * 16 + d0 + lrow) * 80u + kbyte;
                    ldsm4(ar[s], ad);
                }
                #pragma unroll
                for (int ci = 0; ci < 6; ci++) {
                    if (ci >= NCOMBO) break;
                    const int bk = (ci == 0) ? 0 : 1;
                    #pragma unroll
                    for (int nj = 0; nj < 4; nj++) {
                        uint32_t bfrag[2] = { br[CB[ci]][nj >> 1][nj & 1],
                                              br[CB[ci]][nj >> 1][(nj & 1) + 2] };
                        mma16816(acc[bk][mi][nj], ar[CA[ci]], bfrag);
                    }
                }
            }
        }

        if (c + 1 < NC) store_chunk((c + 1) & 1);
        __syncthreads();
    }

    // ---- epilogue: accH + accL + bias, act, store ----
    #pragma unroll
    for (int mi = 0; mi < 4; mi++) {
        #pragma unroll
        for (int nj = 0; nj < 4; nj++) {
            int cl   = n_base + nj * 8 + (lane & 3) * 2;
            int colg = col0 + cl;
            if (colg >= N) continue;
            int rg0 = row0 + m_base + mi * 16 + (lane >> 2);
            float b0 = sbias[cl], b1 = sbias[cl + 1];
            float v0 = (acc[0][mi][nj][0] + acc[1][mi][nj][0]) + b0;
            float v1 = (acc[0][mi][nj][1] + acc[1][mi][nj][1]) + b1;
            float v2 = (acc[0][mi][nj][2] + acc[1][mi][nj][2]) + b0;
            float v3 = (acc[0][mi][nj][3] + acc[1][mi][nj][3]) + b1;
            if (ACT == 1) {
                v0 = fmaxf(v0, 0.f); v1 = fmaxf(v1, 0.f);
                v2 = fmaxf(v2, 0.f); v3 = fmaxf(v3, 0.f);
            } else if (ACT == 2) {
                v0 = tanhf(v0); v1 = tanhf(v1);
                v2 = tanhf(v2); v3 = tanhf(v3);
            }
            *(float2*)(C + (size_t)rg0 * N + colg)       = make_float2(v0, v1);
            *(float2*)(C + (size_t)(rg0 + 8) * N + colg) = make_float2(v2, v3);
        }
    }
}

// ---------------------------------------------------------------------------
// VQ (unchanged, passed R2/R3): fp32 top-2 + double rescue on near-ties.
// ---------------------------------------------------------------------------
__global__ __launch_bounds__(256)
void vq_kernel(const float* __restrict__ z_e, const float* __restrict__ E,
               float* __restrict__ zq, int rows_per_block)
{
    extern __shared__ float sm[];
    float* Es   = sm;
    float* zrow = Es + 128 * 129;

    __shared__ float s_e2[128];
    __shared__ float s_rv[8];
    __shared__ int   s_ri[8];
    __shared__ float s_m1v[2];
    __shared__ int   s_m1i[2];
    __shared__ int   s_kmin[8];

    const int tid  = threadIdx.x;
    const int lane = tid & 31;
    const int warp = tid >> 5;
    const int k    = tid & 127;
    const int g    = tid >> 7;
    const float INF = __int_as_float(0x7f800000);
    const float TAU = 0.05f;

    for (int i = tid; i < 128 * 128; i += 256)
        Es[(i >> 7) * 129 + (i & 127)] = E[i];
    __syncthreads();

    if (tid < 128) {
        float s = 0.f;
        #pragma unroll 8
        for (int d = 0; d < 128; d++) {
            float e = Es[d * 129 + tid];
            s = fmaf(e, e, s);
        }
        s_e2[tid] = s;
    }
    __syncthreads();

    const int b0 = blockIdx.x * rows_per_block;
    for (int r = 0; r < rows_per_block; r++) {
        const int b = b0 + r;
        for (int i = tid; i < 1024; i += 256)
            zrow[i] = z_e[(size_t)b * 1024 + i];
        __syncthreads();

        for (int it = 0; it < 4; it++) {
            const int n = it * 2 + g;
            float a0 = 0.f, a1 = 0.f, a2 = 0.f, a3 = 0.f;
            #pragma unroll 8
            for (int d = 0; d < 128; d += 4) {
                a0 = fmaf(Es[(d + 0) * 129 + k], zrow[(d + 0) * 8 + n], a0);
                a1 = fmaf(Es[(d + 1) * 129 + k], zrow[(d + 1) * 8 + n], a1);
                a2 = fmaf(Es[(d + 2) * 129 + k], zrow[(d + 2) * 8 + n], a2);
                a3 = fmaf(Es[(d + 3) * 129 + k], zrow[(d + 3) * 8 + n], a3);
            }
            const float dist = s_e2[k] - 2.0f * ((a0 + a1) + (a2 + a3));

            float v = dist; int bi = k;
            #pragma unroll
            for (int off = 16; off > 0; off >>= 1) {
                float ov = __shfl_down_sync(0xffffffffu, v,  off);
                int   oi = __shfl_down_sync(0xffffffffu, bi, off);
                if (ov < v || (ov == v && oi < bi)) { v = ov; bi = oi; }
            }
            if (lane == 0) { s_rv[warp] = v; s_ri[warp] = bi; }
            __syncthreads();
            if (tid < 2) {
                int base = tid * 4;
                float bv = s_rv[base]; int bk = s_ri[base];
                #pragma unroll
                for (int w2 = 1; w2 < 4; w2++) {
                    float vv = s_rv[base + w2]; int kk2 = s_ri[base + w2];
                    if (vv < bv || (vv == bv && kk2 < bk)) { bv = vv; bk = kk2; }
                }
                s_m1v[tid] = bv; s_m1i[tid] = bk;
            }
            __syncthreads();

            const int idx1 = s_m1i[g];
            float v2 = (k == idx1) ? INF : dist; int bi2 = k;
            #pragma unroll
            for (int off = 16; off > 0; off >>= 1) {
                float ov = __shfl_down_sync(0xffffffffu, v2,  off);
                int   oi = __shfl_down_sync(0xffffffffu, bi2, off);
                if (ov < v2 || (ov == v2 && oi < bi2)) { v2 = ov; bi2 = oi; }
            }
            if (lane == 0) { s_rv[warp] = v2; s_ri[warp] = bi2; }
            __syncthreads();
            if (tid < 2) {
                int base = tid * 4;
                float bv2 = s_rv[base]; int bk2 = s_ri[base];
                #pragma unroll
                for (int w2 = 1; w2 < 4; w2++) {
                    float vv = s_rv[base + w2]; int kk2 = s_ri[base + w2];
                    if (vv < bv2 || (vv == bv2 && kk2 < bk2)) { bv2 = vv; bk2 = kk2; }
                }
                const int slot = it * 2 + tid;
                int i1 = s_m1i[tid], i2 = bk2;
                int kmin = i1;
                if (bv2 - s_m1v[tid] < TAU) {
                    double d1 = 0.0, d2 = 0.0;
                    for (int d = 0; d < 128; d++) {
                        double zd = (double)zrow[d * 8 + slot];
                        double t1 = zd - (double)Es[d * 129 + i1];
                        double t2 = zd - (double)Es[d * 129 + i2];
                        d1 += t1 * t1;
                        d2 += t2 * t2;
                    }
                    if (d2 < d1 || (d2 == d1 && i2 < i1)) kmin = i2;
                }
                s_kmin[slot] = kmin;
            }
            __syncthreads();
        }

        for (int j = tid; j < 1024; j += 256)
            zq[(size_t)b * 1024 + j] = Es[(j >> 3) * 129 + s_kmin[j & 7]];
        __syncthreads();
    }
}

// ---------------------------------------------------------------------------
// out = [recon (B*784) | z_e (B*1024) | emb (B*1024)]; emb == z_q flat.
// ---------------------------------------------------------------------------
extern "C" void kernel_launch(void* const* d_in, const int* in_sizes, int n_in,
                              void* d_out, int out_size)
{
    const float* x  = (const float*)d_in[0];
    const float* W1 = (const float*)d_in[1];
    const float* b1 = (const float*)d_in[2];
    const float* W2 = (const float*)d_in[3];
    const float* b2 = (const float*)d_in[4];
    const float* W3 = (const float*)d_in[5];
    const float* b3 = (const float*)d_in[6];
    const float* W4 = (const float*)d_in[7];
    const float* b4 = (const float*)d_in[8];
    const float* E  = (const float*)d_in[9];

    float* out   = (float*)d_out;
    float* recon = out;
    float* z_e   = out + (size_t)BB * IN_DIM;
    float* emb   = z_e + (size_t)BB * H1;

    float *h1p, *h3p;
    cudaGetSymbolAddress((void**)&h1p, g_h1);
    cudaGetSymbolAddress((void**)&h3p, g_h3);

    const int PL  = 128 * 40 * 2;
    const int SM3 = 2 * 3 * 2 * PL;   // 122880
    const int SM2 = 2 * 2 * 2 * PL;   // 81920
    cudaFuncSetAttribute(hmma_gemm<3, 1>, cudaFuncAttributeMaxDynamicSharedMemorySize, SM3);
    cudaFuncSetAttribute(hmma_gemm<3, 0>, cudaFuncAttributeMaxDynamicSharedMemorySize, SM3);
    cudaFuncSetAttribute(hmma_gemm<2, 1>, cudaFuncAttributeMaxDynamicSharedMemorySize, SM2);
    cudaFuncSetAttribute(hmma_gemm<2, 2>, cudaFuncAttributeMaxDynamicSharedMemorySize, SM2);

    // G1: h1 = relu(x @ W1 + b1)   [3-split, 2 acc banks]
    hmma_gemm<3, 1><<<dim3(H0 / 128, BB / 128), 256, SM3>>>(x, W1, b1, h1p, BB, H0, IN_DIM);
    // G2: z_e = h1 @ W2 + b2       [3-split, 2 acc banks]
    hmma_gemm<3, 0><<<dim3(H1 / 128, BB / 128), 256, SM3>>>(h1p, W2, b2, z_e, BB, H1, H0);

    // VQ
    const int smem = (128 * 129 + 1024) * (int)sizeof(float);
    cudaFuncSetAttribute(vq_kernel, cudaFuncAttributeMaxDynamicSharedMemorySize, smem);
    vq_kernel<<<2048, 256, smem>>>(z_e, E, emb, BB / 2048);

    // G3: h3 = relu(z_q @ W3 + b3) [2-split]
    hmma_gemm<2, 1><<<dim3(H0 / 128, BB / 128), 256, SM2>>>(emb, W3, b3, h3p, BB, H0, H1);
    // G4: recon = tanh(h3 @ W4 + b4)
    hmma_gemm<2, 2><<<dim3((IN_DIM + 127) / 128, BB / 128), 256, SM2>>>(h3p, W4, b4, recon, BB, IN_DIM, H0);
}

// round 8
// speedup vs baseline: 1.2412x; 1.1846x over previous
#include <cuda_runtime.h>
#include <cuda_bf16.h>
#include <math.h>
#include <stdint.h>

#define BB      32768
#define IN_DIM  784
#define H0      512
#define H1      1024

// ---- bf16 plane scratch (static __device__, no runtime alloc) ----
__device__ __align__(16) __nv_bfloat16 g_xs [3][(size_t)BB * IN_DIM];
__device__ __align__(16) __nv_bfloat16 g_h1s[3][(size_t)BB * H0];
__device__ __align__(16) __nv_bfloat16 g_zqs[2][(size_t)BB * H1];
__device__ __align__(16) __nv_bfloat16 g_h3s[2][(size_t)BB * H0];
__device__ __align__(16) __nv_bfloat16 g_W1t[3][(size_t)H0 * IN_DIM];
__device__ __align__(16) __nv_bfloat16 g_W2t[3][(size_t)H1 * H0];
__device__ __align__(16) __nv_bfloat16 g_W3t[2][(size_t)H0 * H1];
__device__ __align__(16) __nv_bfloat16 g_W4t[2][(size_t)IN_DIM * H0];

__device__ __forceinline__ uint32_t smem_u32(const void* p) {
    uint32_t a;
    asm("{ .reg .u64 t; cvta.to.shared.u64 t, %1; cvt.u32.u64 %0, t; }"
        : "=r"(a) : "l"(p));
    return a;
}
__device__ __forceinline__ void ldsm4(uint32_t* r, uint32_t a) {
    asm volatile("ldmatrix.sync.aligned.m8n8.x4.shared.b16 {%0,%1,%2,%3}, [%4];"
                 : "=r"(r[0]), "=r"(r[1]), "=r"(r[2]), "=r"(r[3]) : "r"(a));
}
__device__ __forceinline__ void mma16816(float* d, const uint32_t* a, const uint32_t* b) {
    asm volatile("mma.sync.aligned.m16n8k16.row.col.f32.bf16.bf16.f32 "
                 "{%0,%1,%2,%3}, {%4,%5,%6,%7}, {%8,%9}, {%0,%1,%2,%3};"
                 : "+f"(d[0]), "+f"(d[1]), "+f"(d[2]), "+f"(d[3])
                 : "r"(a[0]), "r"(a[1]), "r"(a[2]), "r"(a[3]), "r"(b[0]), "r"(b[1]));
}
__device__ __forceinline__ void split3(float a, uint32_t& h, uint32_t& m, uint32_t& l) {
    __nv_bfloat16 bh = __float2bfloat16(a);
    float r = a - __bfloat162float(bh);
    __nv_bfloat16 bm = __float2bfloat16(r);
    __nv_bfloat16 bl = __float2bfloat16(r - __bfloat162float(bm));
    h = (uint32_t)__bfloat16_as_ushort(bh);
    m = (uint32_t)__bfloat16_as_ushort(bm);
    l = (uint32_t)__bfloat16_as_ushort(bl);
}

#define CPA16(dst, src, sz) \
    asm volatile("cp.async.cg.shared.global [%0], [%1], 16, %2;" \
                 :: "r"(dst), "l"(src), "r"(sz))
#define CP_COMMIT() asm volatile("cp.async.commit_group;")
#define CP_WAIT0()  asm volatile("cp.async.wait_group 0;")
#define CP_WAIT1()  asm volatile("cp.async.wait_group 1;")

// ---------------------------------------------------------------------------
// Elementwise 3-split: in fp32 -> 3 bf16 planes.
// ---------------------------------------------------------------------------
__global__ void split3_elem(const float* __restrict__ in, __nv_bfloat16* __restrict__ o0,
                            __nv_bfloat16* __restrict__ o1, __nv_bfloat16* __restrict__ o2,
                            size_t n)
{
    size_t i = (size_t)blockIdx.x * blockDim.x + threadIdx.x;
    size_t st = (size_t)gridDim.x * blockDim.x;
    for (; i < n; i += st) {
        uint32_t h, m, l;
        split3(in[i], h, m, l);
        o0[i] = __ushort_as_bfloat16((unsigned short)h);
        o1[i] = __ushort_as_bfloat16((unsigned short)m);
        o2[i] = __ushort_as_bfloat16((unsigned short)l);
    }
}

// ---------------------------------------------------------------------------
// Transpose + split: W [K][N] fp32 -> NS planes [N][K] bf16.
// ---------------------------------------------------------------------------
template<int NS>
__global__ void tsplit(const float* __restrict__ W, __nv_bfloat16* __restrict__ o0,
                       __nv_bfloat16* __restrict__ o1, __nv_bfloat16* __restrict__ o2,
                       int K, int N)
{
    __shared__ float t[32][33];
    int kb = blockIdx.x * 32, nb = blockIdx.y * 32;
    int tx = threadIdx.x, ty = threadIdx.y;     // 32 x 8
    for (int i = ty; i < 32; i += 8) {
        int k = kb + i, n = nb + tx;
        t[i][tx] = (k < K && n < N) ? W[(size_t)k * N + n] : 0.0f;
    }
    __syncthreads();
    for (int i = ty; i < 32; i += 8) {
        int n = nb + i, k = kb + tx;
        if (n < N && k < K) {
            uint32_t h, m, l;
            split3(t[tx][i], h, m, l);
            size_t off = (size_t)n * K + k;
            o0[off] = __ushort_as_bfloat16((unsigned short)h);
            o1[off] = __ushort_as_bfloat16((unsigned short)m);
            if (NS == 3) o2[off] = __ushort_as_bfloat16((unsigned short)l);
        }
    }
}

// ===========================================================================
// HMMA GEMM on pre-split bf16 planes.
// C = act(A @ B^T + bias) with A planes [M][K], B planes [N][K] (pre-transposed).
// CTA 128x128, 8 warps (64x32 each), K-chunk 32, cp.async double buffer.
// NS: #planes per operand. NB: acc banks (2: hh isolated -> fp32-class error).
// Combos: NS3 -> hh|hm,mh,mm,hl,lh ; NS2 -> hh|hm,mh.
// OS: 0 -> write fp32 Cf; 2/3 -> write OS bf16 output planes P0..P2.
// ACT: 0 none, 1 relu, 2 tanh.  MC: min CTAs/SM for launch_bounds.
// ===========================================================================
template<int NS, int NB, int ACT, int OS, int MC>
__global__ __launch_bounds__(256, MC)
void hmma_gemm(const __nv_bfloat16* __restrict__ A0, const __nv_bfloat16* __restrict__ A1,
               const __nv_bfloat16* __restrict__ A2,
               const __nv_bfloat16* __restrict__ B0, const __nv_bfloat16* __restrict__ B1,
               const __nv_bfloat16* __restrict__ B2,
               const float* __restrict__ bias, float* __restrict__ Cf,
               __nv_bfloat16* __restrict__ P0, __nv_bfloat16* __restrict__ P1,
               __nv_bfloat16* __restrict__ P2,
               int M, int N, int K)
{
    constexpr int PL    = 128 * 40 * 2;      // 10240 B plane tile (pad-40 rows)
    constexpr int BUFSZ = NS * 2 * PL;
    extern __shared__ char dsm[];
    const uint32_t smemU = smem_u32(dsm);
    __shared__ float sbias[128];

    const int tid  = threadIdx.x;
    const int warp = tid >> 5;
    const int lane = tid & 31;
    const int row0 = blockIdx.y * 128;
    const int col0 = blockIdx.x * 128;
    const int m_base = (warp >> 2) * 64;
    const int n_base = (warp & 3) * 32;

    {
        int c = col0 + tid;
        if (tid < 128) sbias[tid] = (c < N) ? bias[c] : 0.0f;
    }

    const __nv_bfloat16* Ap[3] = {A0, A1, A2};
    const __nv_bfloat16* Bp[3] = {B0, B1, B2};

    const int CA[6] = {0, 0, 1, 1, 0, 2};
    const int CB[6] = {0, 1, 0, 1, 2, 0};
    constexpr int NCOMBO = (NS == 3) ? 6 : 3;

    float acc[NB][4][4][4];
    #pragma unroll
    for (int bk = 0; bk < NB; bk++)
        #pragma unroll
        for (int i = 0; i < 4; i++)
            #pragma unroll
            for (int j = 0; j < 4; j++)
                #pragma unroll
                for (int q = 0; q < 4; q++) acc[bk][i][j][q] = 0.0f;

    const int NC = (K + 31) >> 5;

    auto load_chunk = [&](int c, int buf) {
        const int k0 = c << 5;
        const uint32_t bu = smemU + buf * BUFSZ;
        #pragma unroll
        for (int p = 0; p < NS; p++) {
            #pragma unroll
            for (int it = 0; it < 2; it++) {
                int idx = it * 256 + tid;
                int r = idx >> 2, seg = idx & 3;
                int kk = k0 + seg * 8;
                bool ak = (kk < K);
                const void* sA = ak ? (const void*)(Ap[p] + (size_t)(row0 + r) * K + kk)
                                    : (const void*)Ap[p];
                CPA16(bu + p * PL + (uint32_t)(r * 80 + seg * 16), sA, ak ? 16u : 0u);
                bool bk2 = ak && (col0 + r) < N;
                const void* sB = bk2 ? (const void*)(Bp[p] + (size_t)(col0 + r) * K + kk)
                                     : (const void*)Bp[p];
                CPA16(bu + (NS + p) * PL + (uint32_t)(r * 80 + seg * 16), sB, bk2 ? 16u : 0u);
            }
        }
    };

    const int lgrp = lane >> 3, lrow = lane & 7;
    const int d0 = (lgrp & 1) * 8;
    const int dk = (lgrp >> 1) * 8;

    load_chunk(0, 0);
    CP_COMMIT();

    for (int c = 0; c < NC; c++) {
        if (c + 1 < NC) { load_chunk(c + 1, (c + 1) & 1); CP_COMMIT(); CP_WAIT1(); }
        else            { CP_WAIT0(); }
        __syncthreads();

        const uint32_t bu = smemU + (c & 1) * BUFSZ;
        #pragma unroll
        for (int ks = 0; ks < 2; ks++) {
            const uint32_t kbyte = (uint32_t)(ks * 16 + dk) * 2u;
            uint32_t br[NS][2][4];
            #pragma unroll
            for (int s = 0; s < NS; s++)
                #pragma unroll
                for (int ni = 0; ni < 2; ni++) {
                    uint32_t ad = bu + (NS + s) * PL
                                + (uint32_t)(n_base + ni * 16 + d0 + lrow) * 80u + kbyte;
                    ldsm4(br[s][ni], ad);
                }
            #pragma unroll
            for (int mi = 0; mi < 4; mi++) {
                uint32_t ar[NS][4];
                #pragma unroll
                for (int s = 0; s < NS; s++) {
                    uint32_t ad = bu + s * PL
                                + (uint32_t)(m_base + mi * 16 + d0 + lrow) * 80u + kbyte;
                    ldsm4(ar[s], ad);
                }
                #pragma unroll
                for (int ci = 0; ci < 6; ci++) {
                    if (ci >= NCOMBO) break;
                    const int bk = (NB == 2 && ci > 0) ? 1 : 0;
                    #pragma unroll
                    for (int nj = 0; nj < 4; nj++) {
                        uint32_t bfrag[2] = { br[CB[ci]][nj >> 1][nj & 1],
                                              br[CB[ci]][nj >> 1][(nj & 1) + 2] };
                        mma16816(acc[bk][mi][nj], ar[CA[ci]], bfrag);
                    }
                }
            }
        }
        __syncthreads();
    }

    // ---- epilogue ----
    #pragma unroll
    for (int mi = 0; mi < 4; mi++) {
        #pragma unroll
        for (int nj = 0; nj < 4; nj++) {
            int cl   = n_base + nj * 8 + (lane & 3) * 2;
            int colg = col0 + cl;
            if (colg >= N) continue;
            int rg0 = row0 + m_base + mi * 16 + (lane >> 2);
            float b0 = sbias[cl], b1 = sbias[cl + 1];
            float v0 = acc[0][mi][nj][0], v1 = acc[0][mi][nj][1];
            float v2 = acc[0][mi][nj][2], v3 = acc[0][mi][nj][3];
            if (NB == 2) {
                v0 += acc[1][mi][nj][0]; v1 += acc[1][mi][nj][1];
                v2 += acc[1][mi][nj][2]; v3 += acc[1][mi][nj][3];
            }
            v0 += b0; v1 += b1; v2 += b0; v3 += b1;
            if (ACT == 1) {
                v0 = fmaxf(v0, 0.f); v1 = fmaxf(v1, 0.f);
                v2 = fmaxf(v2, 0.f); v3 = fmaxf(v3, 0.f);
            } else if (ACT == 2) {
                v0 = tanhf(v0); v1 = tanhf(v1);
                v2 = tanhf(v2); v3 = tanhf(v3);
            }
            if (OS == 0) {
                *(float2*)(Cf + (size_t)rg0 * N + colg)       = make_float2(v0, v1);
                *(float2*)(Cf + (size_t)(rg0 + 8) * N + colg) = make_float2(v2, v3);
            } else {
                uint32_t h0, m0, l0, h1, m1, l1;
                split3(v0, h0, m0, l0); split3(v1, h1, m1, l1);
                size_t o = (size_t)rg0 * N + colg;
                *(uint32_t*)(P0 + o) = h0 | (h1 << 16);
                *(uint32_t*)(P1 + o) = m0 | (m1 << 16);
                if (OS == 3) *(uint32_t*)(P2 + o) = l0 | (l1 << 16);
                split3(v2, h0, m0, l0); split3(v3, h1, m1, l1);
                o = (size_t)(rg0 + 8) * N + colg;
                *(uint32_t*)(P0 + o) = h0 | (h1 << 16);
                *(uint32_t*)(P1 + o) = m0 | (m1 << 16);
                if (OS == 3) *(uint32_t*)(P2 + o) = l0 | (l1 << 16);
            }
        }
    }
}

// ---------------------------------------------------------------------------
// VQ (R2-validated core) + writes z_q as 2 bf16 planes for G3.
// ---------------------------------------------------------------------------
__global__ __launch_bounds__(256)
void vq_kernel(const float* __restrict__ z_e, const float* __restrict__ E,
               float* __restrict__ zq, __nv_bfloat16* __restrict__ zqh,
               __nv_bfloat16* __restrict__ zqm, int rows_per_block)
{
    extern __shared__ float sm[];
    float* Es   = sm;
    float* zrow = Es + 128 * 129;

    __shared__ float s_e2[128];
    __shared__ float s_rv[8];
    __shared__ int   s_ri[8];
    __shared__ float s_m1v[2];
    __shared__ int   s_m1i[2];
    __shared__ int   s_kmin[8];

    const int tid  = threadIdx.x;
    const int lane = tid & 31;
    const int warp = tid >> 5;
    const int k    = tid & 127;
    const int g    = tid >> 7;
    const float INF = __int_as_float(0x7f800000);
    const float TAU = 0.05f;

    for (int i = tid; i < 128 * 128; i += 256)
        Es[(i >> 7) * 129 + (i & 127)] = E[i];
    __syncthreads();

    if (tid < 128) {
        float s = 0.f;
        #pragma unroll 8
        for (int d = 0; d < 128; d++) {
            float e = Es[d * 129 + tid];
            s = fmaf(e, e, s);
        }
        s_e2[tid] = s;
    }
    __syncthreads();

    const int b0 = blockIdx.x * rows_per_block;
    for (int r = 0; r < rows_per_block; r++) {
        const int b = b0 + r;
        for (int i = tid; i < 1024; i += 256)
            zrow[i] = z_e[(size_t)b * 1024 + i];
        __syncthreads();

        for (int it = 0; it < 4; it++) {
            const int n = it * 2 + g;
            float a0 = 0.f, a1 = 0.f, a2 = 0.f, a3 = 0.f;
            #pragma unroll 8
            for (int d = 0; d < 128; d += 4) {
                a0 = fmaf(Es[(d + 0) * 129 + k], zrow[(d + 0) * 8 + n], a0);
                a1 = fmaf(Es[(d + 1) * 129 + k], zrow[(d + 1) * 8 + n], a1);
                a2 = fmaf(Es[(d + 2) * 129 + k], zrow[(d + 2) * 8 + n], a2);
                a3 = fmaf(Es[(d + 3) * 129 + k], zrow[(d + 3) * 8 + n], a3);
            }
            const float dist = s_e2[k] - 2.0f * ((a0 + a1) + (a2 + a3));

            float v = dist; int bi = k;
            #pragma unroll
            for (int off = 16; off > 0; off >>= 1) {
                float ov = __shfl_down_sync(0xffffffffu, v,  off);
                int   oi = __shfl_down_sync(0xffffffffu, bi, off);
                if (ov < v || (ov == v && oi < bi)) { v = ov; bi = oi; }
            }
            if (lane == 0) { s_rv[warp] = v; s_ri[warp] = bi; }
            __syncthreads();
            if (tid < 2) {
                int base = tid * 4;
                float bv = s_rv[base]; int bk = s_ri[base];
                #pragma unroll
                for (int w2 = 1; w2 < 4; w2++) {
                    float vv = s_rv[base + w2]; int kk2 = s_ri[base + w2];
                    if (vv < bv || (vv == bv && kk2 < bk)) { bv = vv; bk = kk2; }
                }
                s_m1v[tid] = bv; s_m1i[tid] = bk;
            }
            __syncthreads();

            const int idx1 = s_m1i[g];
            float v2 = (k == idx1) ? INF : dist; int bi2 = k;
            #pragma unroll
            for (int off = 16; off > 0; off >>= 1) {
                float ov = __shfl_down_sync(0xffffffffu, v2,  off);
                int   oi = __shfl_down_sync(0xffffffffu, bi2, off);
                if (ov < v2 || (ov == v2 && oi < bi2)) { v2 = ov; bi2 = oi; }
            }
            if (lane == 0) { s_rv[warp] = v2; s_ri[warp] = bi2; }
            __syncthreads();
            if (tid < 2) {
                int base = tid * 4;
                float bv2 = s_rv[base]; int bk2 = s_ri[base];
                #pragma unroll
                for (int w2 = 1; w2 < 4; w2++) {
                    float vv = s_rv[base + w2]; int kk2 = s_ri[base + w2];
                    if (vv < bv2 || (vv == bv2 && kk2 < bk2)) { bv2 = vv; bk2 = kk2; }
                }
                const int slot = it * 2 + tid;
                int i1 = s_m1i[tid], i2 = bk2;
                int kmin = i1;
                if (bv2 - s_m1v[tid] < TAU) {
                    double d1 = 0.0, d2 = 0.0;
                    for (int d = 0; d < 128; d++) {
                        double zd = (double)zrow[d * 8 + slot];
                        double t1 = zd - (double)Es[d * 129 + i1];
                        double t2 = zd - (double)Es[d * 129 + i2];
                        d1 += t1 * t1;
                        d2 += t2 * t2;
                    }
                    if (d2 < d1 || (d2 == d1 && i2 < i1)) kmin = i2;
                }
                s_kmin[slot] = kmin;
            }
            __syncthreads();
        }

        for (int j = tid; j < 1024; j += 256) {
            float val = Es[(j >> 3) * 129 + s_kmin[j & 7]];
            size_t o = (size_t)b * 1024 + j;
            zq[o] = val;
            __nv_bfloat16 h = __float2bfloat16(val);
            zqh[o] = h;
            zqm[o] = __float2bfloat16(val - __bfloat162float(h));
        }
        __syncthreads();
    }
}

// ---------------------------------------------------------------------------
// out = [recon (B*784) | z_e (B*1024) | emb (B*1024)]; emb == z_q flat.
// ---------------------------------------------------------------------------
extern "C" void kernel_launch(void* const* d_in, const int* in_sizes, int n_in,
                              void* d_out, int out_size)
{
    const float* x  = (const float*)d_in[0];
    const float* W1 = (const float*)d_in[1];
    const float* b1 = (const float*)d_in[2];
    const float* W2 = (const float*)d_in[3];
    const float* b2 = (const float*)d_in[4];
    const float* W3 = (const float*)d_in[5];
    const float* b3 = (const float*)d_in[6];
    const float* W4 = (const float*)d_in[7];
    const float* b4 = (const float*)d_in[8];
    const float* E  = (const float*)d_in[9];

    float* out   = (float*)d_out;
    float* recon = out;
    float* z_e   = out + (size_t)BB * IN_DIM;
    float* emb   = z_e + (size_t)BB * H1;

    __nv_bfloat16 *xs, *h1s, *zqs, *h3s, *w1t, *w2t, *w3t, *w4t;
    cudaGetSymbolAddress((void**)&xs,  g_xs);
    cudaGetSymbolAddress((void**)&h1s, g_h1s);
    cudaGetSymbolAddress((void**)&zqs, g_zqs);
    cudaGetSymbolAddress((void**)&h3s, g_h3s);
    cudaGetSymbolAddress((void**)&w1t, g_W1t);
    cudaGetSymbolAddress((void**)&w2t, g_W2t);
    cudaGetSymbolAddress((void**)&w3t, g_W3t);
    cudaGetSymbolAddress((void**)&w4t, g_W4t);
    const size_t NX = (size_t)BB * IN_DIM, NH0 = (size_t)BB * H0, NH1 = (size_t)BB * H1;
    const size_t SW1 = (size_t)H0 * IN_DIM, SW2 = (size_t)H1 * H0;
    const size_t SW3 = (size_t)H0 * H1,     SW4 = (size_t)IN_DIM * H0;

    // ---- pre-split inputs/weights ----
    split3_elem<<<2048, 256>>>(x, xs, xs + NX, xs + 2 * NX, NX);
    dim3 tb(32, 8);
    tsplit<3><<<dim3(25, 16), tb>>>(W1, w1t, w1t + SW1, w1t + 2 * SW1, IN_DIM, H0);
    tsplit<3><<<dim3(16, 32), tb>>>(W2, w2t, w2t + SW2, w2t + 2 * SW2, H0, H1);
    tsplit<2><<<dim3(32, 16), tb>>>(W3, w3t, w3t + SW3, nullptr, H1, H0);
    tsplit<2><<<dim3(16, 25), tb>>>(W4, w4t, w4t + SW4, nullptr, H0, IN_DIM);

    const int PL  = 128 * 40 * 2;
    const int SM3 = 2 * 3 * 2 * PL;   // 122880
    const int SM2 = 2 * 2 * 2 * PL;   // 81920
    cudaFuncSetAttribute(hmma_gemm<3, 2, 1, 3, 1>, cudaFuncAttributeMaxDynamicSharedMemorySize, SM3);
    cudaFuncSetAttribute(hmma_gemm<3, 2, 0, 0, 1>, cudaFuncAttributeMaxDynamicSharedMemorySize, SM3);
    cudaFuncSetAttribute(hmma_gemm<2, 1, 1, 2, 2>, cudaFuncAttributeMaxDynamicSharedMemorySize, SM2);
    cudaFuncSetAttribute(hmma_gemm<2, 1, 2, 0, 2>, cudaFuncAttributeMaxDynamicSharedMemorySize, SM2);

    // G1: h1 = relu(x @ W1 + b1) -> 3 planes
    hmma_gemm<3, 2, 1, 3, 1><<<dim3(H0 / 128, BB / 128), 256, SM3>>>(
        xs, xs + NX, xs + 2 * NX, w1t, w1t + SW1, w1t + 2 * SW1,
        b1, nullptr, h1s, h1s + NH0, h1s + 2 * NH0, BB, H0, IN_DIM);
    // G2: z_e = h1 @ W2 + b2 -> fp32 (d_out)
    hmma_gemm<3, 2, 0, 0, 1><<<dim3(H1 / 128, BB / 128), 256, SM3>>>(
        h1s, h1s + NH0, h1s + 2 * NH0, w2t, w2t + SW2, w2t + 2 * SW2,
        b2, z_e, nullptr, nullptr, nullptr, BB, H1, H0);

    // VQ -> emb fp32 + z_q planes
    const int smem = (128 * 129 + 1024) * (int)sizeof(float);
    cudaFuncSetAttribute(vq_kernel, cudaFuncAttributeMaxDynamicSharedMemorySize, smem);
    vq_kernel<<<2048, 256, smem>>>(z_e, E, emb, zqs, zqs + NH1, BB / 2048);

    // G3: h3 = relu(z_q @ W3 + b3) -> 2 planes
    hmma_gemm<2, 1, 1, 2, 2><<<dim3(H0 / 128, BB / 128), 256, SM2>>>(
        zqs, zqs + NH1, nullptr, w3t, w3t + SW3, nullptr,
        b3, nullptr, h3s, h3s + NH0, nullptr, BB, H0, H1);
    // G4: recon = tanh(h3 @ W4 + b4) -> fp32 (d_out)
    hmma_gemm<2, 1, 2, 0, 2><<<dim3((IN_DIM + 127) / 128, BB / 128), 256, SM2>>>(
        h3s, h3s + NH0, nullptr, w4t, w4t + SW4, nullptr,
        b4, recon, nullptr, nullptr, nullptr, BB, IN_DIM, H0);
}